// round 5
// baseline (speedup 1.0000x reference)
#include <cuda_runtime.h>
#include <cstdint>

// Problem constants
#define B_  32768
#define D_  512
#define E_  10
#define H_  128
#define L_  2
#define RH1_ 256
#define RH2_ 128

// Scratch (allocation-free rule: __device__ globals)
__device__ float g_rh1[(size_t)B_ * RH1_];          // 33.5 MB
__device__ float g_rh2[(size_t)B_ * RH2_];          // 16.8 MB
__device__ float g_h1 [(size_t)E_ * B_ * H_];       // 168 MB

// ---------------------------------------------------------------------------
// Generic tiled SGEMM with bias + ReLU.
// C[M,N] = relu(A[M,K] @ B[K,N] + bias[N]); all row-major.
// Batched over blockIdx.z via element strides (sAe/sBe/sBiasE/sCe).
// BM=BN=128, BK=16, 256 threads, 8x8 per thread. M multiple of 128 (grid.y),
// N multiple of 128 (grid.x), K multiple of 16.
// ---------------------------------------------------------------------------
__global__ __launch_bounds__(256) void sgemm_relu(
    const float* __restrict__ A, const float* __restrict__ Bm,
    const float* __restrict__ bias, float* __restrict__ C,
    int K, int N,
    long long sAe, long long sBe, int sBiasE, long long sCe)
{
    __shared__ float As[16][129];   // transposed A tile, padded (bank spread)
    __shared__ float Bs[16][128];

    const int tid = threadIdx.x;
    const int tx = tid & 15;        // 0..15 -> column group
    const int ty = tid >> 4;        // 0..15 -> row group

    const float* Ab = A + (long long)blockIdx.z * sAe + (long long)blockIdx.y * 128 * K;
    const float* Bb = Bm + (long long)blockIdx.z * sBe + blockIdx.x * 128;
    const float* biasb = bias + (long long)blockIdx.z * sBiasE + blockIdx.x * 128;
    float* Cb = C + (long long)blockIdx.z * sCe + (long long)blockIdx.y * 128 * N + blockIdx.x * 128;

    float acc[8][8];
#pragma unroll
    for (int i = 0; i < 8; i++)
#pragma unroll
        for (int j = 0; j < 8; j++) acc[i][j] = 0.f;

    for (int kt = 0; kt < K; kt += 16) {
        // Load A tile 128x16 (2 x float4 per thread), store transposed
#pragma unroll
        for (int i = 0; i < 2; i++) {
            int s  = tid + i * 256;
            int r  = s >> 2;                 // 0..127
            int c4 = (s & 3) << 2;           // 0,4,8,12
            float4 v = *reinterpret_cast<const float4*>(Ab + (long long)r * K + kt + c4);
            As[c4 + 0][r] = v.x;
            As[c4 + 1][r] = v.y;
            As[c4 + 2][r] = v.z;
            As[c4 + 3][r] = v.w;
        }
        // Load B tile 16x128 (2 x float4 per thread)
#pragma unroll
        for (int i = 0; i < 2; i++) {
            int s = tid + i * 256;
            int r = s >> 5;                  // 0..15
            int c = (s & 31) << 2;           // 0..124
            *reinterpret_cast<float4*>(&Bs[r][c]) =
                *reinterpret_cast<const float4*>(Bb + (long long)(kt + r) * N + c);
        }
        __syncthreads();

#pragma unroll
        for (int k = 0; k < 16; k++) {
            float a[8], b[8];
#pragma unroll
            for (int i = 0; i < 8; i++) a[i] = As[k][ty * 8 + i];
#pragma unroll
            for (int j = 0; j < 8; j++) b[j] = Bs[k][tx * 8 + j];
#pragma unroll
            for (int i = 0; i < 8; i++)
#pragma unroll
                for (int j = 0; j < 8; j++)
                    acc[i][j] += a[i] * b[j];
        }
        __syncthreads();
    }

    float bj[8];
#pragma unroll
    for (int j = 0; j < 8; j++) bj[j] = biasb[tx * 8 + j];

#pragma unroll
    for (int i = 0; i < 8; i++) {
        float* crow = Cb + (long long)(ty * 8 + i) * N + tx * 8;
        float4 v0, v1;
        v0.x = fmaxf(acc[i][0] + bj[0], 0.f);
        v0.y = fmaxf(acc[i][1] + bj[1], 0.f);
        v0.z = fmaxf(acc[i][2] + bj[2], 0.f);
        v0.w = fmaxf(acc[i][3] + bj[3], 0.f);
        v1.x = fmaxf(acc[i][4] + bj[4], 0.f);
        v1.y = fmaxf(acc[i][5] + bj[5], 0.f);
        v1.z = fmaxf(acc[i][6] + bj[6], 0.f);
        v1.w = fmaxf(acc[i][7] + bj[7], 0.f);
        *reinterpret_cast<float4*>(crow)     = v0;
        *reinterpret_cast<float4*>(crow + 4) = v1;
    }
}

// ---------------------------------------------------------------------------
// Router final layer + gumbel softmax.
// logits[b,:] = rh2[b,:] @ rw3 + rb3 ; weights = softmax((logits + g)/tau)
// One thread per row b.
// ---------------------------------------------------------------------------
__global__ __launch_bounds__(256) void router_final_kernel(
    const float* __restrict__ C2, const float* __restrict__ rw3,
    const float* __restrict__ rb3, const float* __restrict__ u,
    float* __restrict__ weights)
{
    __shared__ float w3s[RH2_ * E_];
    __shared__ float b3s[E_];
    const int tid = threadIdx.x;
    for (int i = tid; i < RH2_ * E_; i += 256) w3s[i] = rw3[i];
    if (tid < E_) b3s[tid] = rb3[tid];
    __syncthreads();

    const int b = blockIdx.x * 256 + tid;
    float logit[E_];
#pragma unroll
    for (int e = 0; e < E_; e++) logit[e] = b3s[e];

    const float* row = C2 + (size_t)b * RH2_;
#pragma unroll 4
    for (int i = 0; i < RH2_; i++) {
        float xv = __ldg(row + i);
#pragma unroll
        for (int e = 0; e < E_; e++) logit[e] += xv * w3s[i * E_ + e];
    }

    float s[E_];
    float m = -1e30f;
#pragma unroll
    for (int e = 0; e < E_; e++) {
        float uu = __ldg(u + (size_t)b * E_ + e);
        uu = fminf(fmaxf(uu, 1e-10f), 1.0f);
        float g = -logf(-logf(uu) + 1e-10f);
        s[e] = (logit[e] + g) * (1.0f / 3.0f);
        m = fmaxf(m, s[e]);
    }
    float sum = 0.f;
#pragma unroll
    for (int e = 0; e < E_; e++) { float ev = expf(s[e] - m); s[e] = ev; sum += ev; }
    float inv = 1.0f / sum;
#pragma unroll
    for (int e = 0; e < E_; e++) weights[(size_t)b * E_ + e] = s[e] * inv;
}

// ---------------------------------------------------------------------------
// Fused expert layer2 + layer3:
//   h2 = relu(h1_e @ ew2[e] + eb2[e])   (128x128 tile in registers)
//   zc = h2 @ ew3[e] + eb3[e]           (N=2, cross-thread SMEM reduction)
// Writes chart_outputs[e, b, l].
// ---------------------------------------------------------------------------
__global__ __launch_bounds__(256) void expert23_kernel(
    const float* __restrict__ H1, const float* __restrict__ ew2,
    const float* __restrict__ eb2, const float* __restrict__ ew3,
    const float* __restrict__ eb3, float* __restrict__ co)
{
    __shared__ float As[16][129];
    __shared__ float Bs[16][128];
    __shared__ float w3s[H_ * L_];       // ew3[e] : [128,2]
    __shared__ float red[L_ * 128 * 16]; // partial zc sums

    const int e = blockIdx.y;
    const int tid = threadIdx.x;
    const int tx = tid & 15, ty = tid >> 4;

    const float* Ab = H1 + (size_t)e * B_ * H_ + (size_t)blockIdx.x * 128 * H_;
    const float* Bb = ew2 + (size_t)e * H_ * H_;

    w3s[tid] = ew3[e * H_ * L_ + tid];   // 256 threads = 256 elements exactly

    float acc[8][8];
#pragma unroll
    for (int i = 0; i < 8; i++)
#pragma unroll
        for (int j = 0; j < 8; j++) acc[i][j] = 0.f;

    for (int kt = 0; kt < H_; kt += 16) {
#pragma unroll
        for (int i = 0; i < 2; i++) {
            int s  = tid + i * 256;
            int r  = s >> 2;
            int c4 = (s & 3) << 2;
            float4 v = *reinterpret_cast<const float4*>(Ab + (size_t)r * H_ + kt + c4);
            As[c4 + 0][r] = v.x;
            As[c4 + 1][r] = v.y;
            As[c4 + 2][r] = v.z;
            As[c4 + 3][r] = v.w;
        }
#pragma unroll
        for (int i = 0; i < 2; i++) {
            int s = tid + i * 256;
            int r = s >> 5;
            int c = (s & 31) << 2;
            *reinterpret_cast<float4*>(&Bs[r][c]) =
                *reinterpret_cast<const float4*>(Bb + (size_t)(kt + r) * H_ + c);
        }
        __syncthreads();
#pragma unroll
        for (int k = 0; k < 16; k++) {
            float a[8], b[8];
#pragma unroll
            for (int i = 0; i < 8; i++) a[i] = As[k][ty * 8 + i];
#pragma unroll
            for (int j = 0; j < 8; j++) b[j] = Bs[k][tx * 8 + j];
#pragma unroll
            for (int i = 0; i < 8; i++)
#pragma unroll
                for (int j = 0; j < 8; j++)
                    acc[i][j] += a[i] * b[j];
        }
        __syncthreads();
    }

    // bias + relu -> h2 in registers
    float b2[8];
#pragma unroll
    for (int j = 0; j < 8; j++) b2[j] = eb2[e * H_ + tx * 8 + j];
#pragma unroll
    for (int i = 0; i < 8; i++)
#pragma unroll
        for (int j = 0; j < 8; j++)
            acc[i][j] = fmaxf(acc[i][j] + b2[j], 0.f);

    // partial zc over this thread's 8 columns
#pragma unroll
    for (int i = 0; i < 8; i++) {
        float p0 = 0.f, p1 = 0.f;
#pragma unroll
        for (int j = 0; j < 8; j++) {
            int c = tx * 8 + j;
            p0 += acc[i][j] * w3s[2 * c + 0];
            p1 += acc[i][j] * w3s[2 * c + 1];
        }
        int row = ty * 8 + i;
        red[row * 16 + tx]        = p0;
        red[2048 + row * 16 + tx] = p1;
    }
    __syncthreads();

    // 256 outputs: (row, l)
    const int row = tid >> 1;
    const int l   = tid & 1;
    float s = eb3[e * L_ + l];
#pragma unroll
    for (int t = 0; t < 16; t++) s += red[l * 2048 + row * 16 + t];
    size_t gb = (size_t)blockIdx.x * 128 + row;
    co[(size_t)e * B_ * L_ + gb * L_ + l] = s;
}

// ---------------------------------------------------------------------------
// z[b,l] = sum_e weights[b,e] * co[e,b,l]
// ---------------------------------------------------------------------------
__global__ __launch_bounds__(256) void combine_kernel(
    const float* __restrict__ weights, const float* __restrict__ co,
    float* __restrict__ z)
{
    int idx = blockIdx.x * 256 + threadIdx.x;   // 0 .. B*L-1
    if (idx >= B_ * L_) return;
    int b = idx >> 1;
    float s = 0.f;
#pragma unroll
    for (int e = 0; e < E_; e++)
        s += weights[(size_t)b * E_ + e] * co[(size_t)e * (B_ * L_) + idx];
    z[idx] = s;
}

// ---------------------------------------------------------------------------
extern "C" void kernel_launch(void* const* d_in, const int* in_sizes, int n_in,
                              void* d_out, int out_size)
{
    const float* x   = (const float*)d_in[0];
    const float* u   = (const float*)d_in[1];
    const float* rw1 = (const float*)d_in[2];
    const float* rb1 = (const float*)d_in[3];
    const float* rw2 = (const float*)d_in[4];
    const float* rb2 = (const float*)d_in[5];
    const float* rw3 = (const float*)d_in[6];
    const float* rb3 = (const float*)d_in[7];
    const float* ew1 = (const float*)d_in[8];
    const float* eb1 = (const float*)d_in[9];
    const float* ew2 = (const float*)d_in[10];
    const float* eb2 = (const float*)d_in[11];
    const float* ew3 = (const float*)d_in[12];
    const float* eb3 = (const float*)d_in[13];

    float* out     = (float*)d_out;
    float* z       = out;                                // [B, L]
    float* weights = out + (size_t)B_ * L_;              // [B, E]
    float* co      = weights + (size_t)B_ * E_;          // [E, B, L]

    float *rh1, *rh2, *h1;
    cudaGetSymbolAddress((void**)&rh1, g_rh1);
    cudaGetSymbolAddress((void**)&rh2, g_rh2);
    cudaGetSymbolAddress((void**)&h1,  g_h1);

    // Router layer 1: [B,512] x [512,256] -> rh1
    sgemm_relu<<<dim3(RH1_ / 128, B_ / 128, 1), 256>>>(
        x, rw1, rb1, rh1, D_, RH1_, 0, 0, 0, 0);

    // Router layer 2: [B,256] x [256,128] -> rh2
    sgemm_relu<<<dim3(RH2_ / 128, B_ / 128, 1), 256>>>(
        rh1, rw2, rb2, rh2, RH1_, RH2_, 0, 0, 0, 0);

    // Router layer 3 + gumbel softmax -> weights (d_out)
    router_final_kernel<<<B_ / 256, 256>>>(rh2, rw3, rb3, u, weights);

    // Expert layer 1 (batched over E): [B,512] x [512,128] per expert -> h1[E,B,H]
    sgemm_relu<<<dim3(H_ / 128, B_ / 128, E_), 256>>>(
        x, ew1, eb1, h1, D_, H_,
        /*sAe=*/0, /*sBe=*/(long long)D_ * H_, /*sBiasE=*/H_,
        /*sCe=*/(long long)B_ * H_);

    // Expert layers 2+3 fused -> chart_outputs (d_out)
    expert23_kernel<<<dim3(B_ / 128, E_), 256>>>(h1, ew2, eb2, ew3, eb3, co);

    // Weighted combine -> z (d_out)
    combine_kernel<<<(B_ * L_ + 255) / 256, 256>>>(weights, co, z);
}

// round 9
// speedup vs baseline: 2.3713x; 2.3713x over previous
#include <cuda_runtime.h>
#include <cstdint>

// Problem constants
#define B_   32768
#define D_   512
#define E_   10
#define H_   128
#define L_   2
#define RH1_ 256
#define RH2_ 128

// ---------------------------------------------------------------------------
// Scratch (__device__ globals; allocation-free rule)
// ---------------------------------------------------------------------------
__device__ float g_rh1[(size_t)B_ * RH1_];           // 33.5 MB
__device__ float g_rh2[(size_t)B_ * RH2_];           // 16.8 MB
__device__ float g_h1 [(size_t)E_ * B_ * H_];        // 168 MB
__device__ float g_h2 [(size_t)E_ * B_ * H_];        // 168 MB
// transposed weights: rw1_t[256,512] | rw2_t[128,256] | ew1_t[10,128,512] | ew2_t[10,128,128]
#define WT_RW1 0
#define WT_RW2 131072
#define WT_EW1 163840
#define WT_EW2 819200
__device__ float g_wt[983040];                       // ~3.9 MB

// ---------------------------------------------------------------------------
// Helpers
// ---------------------------------------------------------------------------
__device__ __forceinline__ uint32_t smem_to_u32(const void* p) {
    uint32_t a;
    asm("{ .reg .u64 t; cvta.to.shared.u64 t, %1; cvt.u32.u64 %0, t; }" : "=r"(a) : "l"(p));
    return a;
}
__device__ __forceinline__ void ldsm_x4(uint32_t addr, uint32_t* r) {
    asm volatile("ldmatrix.sync.aligned.m8n8.x4.shared.b16 {%0,%1,%2,%3}, [%4];"
        : "=r"(r[0]), "=r"(r[1]), "=r"(r[2]), "=r"(r[3]) : "r"(addr));
}
__device__ __forceinline__ void mma16816(float* d, const uint32_t* a, uint32_t b0, uint32_t b1) {
    asm volatile("mma.sync.aligned.m16n8k16.row.col.f32.bf16.bf16.f32 "
        "{%0,%1,%2,%3}, {%4,%5,%6,%7}, {%8,%9}, {%0,%1,%2,%3};"
        : "+f"(d[0]), "+f"(d[1]), "+f"(d[2]), "+f"(d[3])
        : "r"(a[0]), "r"(a[1]), "r"(a[2]), "r"(a[3]), "r"(b0), "r"(b1));
}
// pack two fp32 -> bf16x2 (lo element = first arg of pair at low half)
__device__ __forceinline__ uint32_t pack_bf16x2(float lo, float hi) {
    uint32_t r;
    asm("cvt.rn.bf16x2.f32 %0, %1, %2;" : "=r"(r) : "f"(hi), "f"(lo));
    return r;
}

// ---------------------------------------------------------------------------
// Batched transpose: in[e][K][N] -> out[e][N][K]  (K, N multiples of 32)
// ---------------------------------------------------------------------------
__global__ void transpose_kernel(const float* __restrict__ in, float* __restrict__ out,
                                 int K, int N)
{
    __shared__ float t[32][33];
    const size_t eoff = (size_t)blockIdx.z * K * N;
    const int n0 = blockIdx.x * 32, k0 = blockIdx.y * 32;
    const int tx = threadIdx.x, ty = threadIdx.y;  // 32 x 8
#pragma unroll
    for (int i = 0; i < 32; i += 8)
        t[ty + i][tx] = in[eoff + (size_t)(k0 + ty + i) * N + n0 + tx];
    __syncthreads();
#pragma unroll
    for (int i = 0; i < 32; i += 8)
        out[eoff + (size_t)(n0 + ty + i) * K + k0 + tx] = t[tx][ty + i];
}

// ---------------------------------------------------------------------------
// bf16 3-term compensated GEMM + bias + relu via mma.sync (HMMA).
//   C[128,128-tile] = relu(A[M,K] @ Bt[N,K]^T + bias)
// A row-major lda=K; Bt row-major [N][K] (pre-transposed weights).
// grid = (M/128, E, Ntot/128), 256 threads (8 warps: 4 m x 2 n).
// SMEM: double-buffered {Ah, Al, Bh, Bl} tiles, 128 rows x 32 bf16, rows
// padded to 40 bf16 (80B) for conflict-free ldmatrix.
// ---------------------------------------------------------------------------
#define BK      32
#define SK      40                   // padded row stride (bf16 elems)
#define TILE_BYTES_ (128 * SK * 2)   // 10240
#define OFF_AH  0
#define OFF_AL  (1 * TILE_BYTES_)
#define OFF_BH  (2 * TILE_BYTES_)
#define OFF_BL  (3 * TILE_BYTES_)
#define STAGE_B (4 * TILE_BYTES_)    // 40960
#define SMEM_MMA (2 * STAGE_B)       // 81920

__global__ __launch_bounds__(256) void mma_gemm_relu(
    const float* __restrict__ A, const float* __restrict__ Bt,
    const float* __restrict__ bias, float* __restrict__ C,
    int K, int Ntot, long long sAe, long long sBe, int sBiasE, long long sCe)
{
    extern __shared__ char smem[];
    const uint32_t sb = smem_to_u32(smem);
    const int tid = threadIdx.x;
    const int lane = tid & 31, wid = tid >> 5;
    const int warp_m = wid & 3;           // 4 warps over M (32 rows each)
    const int warp_n = wid >> 2;          // 2 warps over N (64 cols each)
    const int e = blockIdx.y, ntile = blockIdx.z;

    const float* Ab = A + (size_t)e * sAe + (size_t)blockIdx.x * 128 * K;
    const float* Bb = Bt + (size_t)e * sBe + (size_t)ntile * 128 * K;

    // global-load coords: 4 float4 each for A and B per chunk
    const int gr = tid >> 3;              // +32 per iter
    const int gc = (tid & 7) << 2;        // fp32 col within chunk (0..28)

    float4 va[4], vb[4];

    const int nk = K >> 5;   // chunks of 32 fp32 K

    float acc[2][8][4];
#pragma unroll
    for (int mt = 0; mt < 2; mt++)
#pragma unroll
        for (int nb = 0; nb < 8; nb++)
#pragma unroll
            for (int q = 0; q < 4; q++) acc[mt][nb][q] = 0.f;

    // ---- load chunk kc globals into registers
    auto issue_loads = [&](int kc) {
#pragma unroll
        for (int i = 0; i < 4; i++) {
            const int r = gr + i * 32;
            va[i] = *reinterpret_cast<const float4*>(Ab + (size_t)r * K + kc * BK + gc);
            vb[i] = *reinterpret_cast<const float4*>(Bb + (size_t)r * K + kc * BK + gc);
        }
    };
    // ---- split to bf16 hi/lo and store to smem stage
    auto store_smem = [&](int stage) {
        const uint32_t base = sb + stage * STAGE_B;
#pragma unroll
        for (int i = 0; i < 4; i++) {
            const int r = gr + i * 32;
            const uint32_t off = (uint32_t)(r * (SK * 2) + gc * 2);
            {
                float4 v = va[i];
                uint32_t h0 = pack_bf16x2(v.x, v.y);
                uint32_t h1 = pack_bf16x2(v.z, v.w);
                float r0 = v.x - __uint_as_float(h0 << 16);
                float r1 = v.y - __uint_as_float(h0 & 0xffff0000u);
                float r2 = v.z - __uint_as_float(h1 << 16);
                float r3 = v.w - __uint_as_float(h1 & 0xffff0000u);
                uint32_t l0 = pack_bf16x2(r0, r1);
                uint32_t l1 = pack_bf16x2(r2, r3);
                asm volatile("st.shared.v2.b32 [%0], {%1,%2};" :: "r"(base + OFF_AH + off), "r"(h0), "r"(h1) : "memory");
                asm volatile("st.shared.v2.b32 [%0], {%1,%2};" :: "r"(base + OFF_AL + off), "r"(l0), "r"(l1) : "memory");
            }
            {
                float4 v = vb[i];
                uint32_t h0 = pack_bf16x2(v.x, v.y);
                uint32_t h1 = pack_bf16x2(v.z, v.w);
                float r0 = v.x - __uint_as_float(h0 << 16);
                float r1 = v.y - __uint_as_float(h0 & 0xffff0000u);
                float r2 = v.z - __uint_as_float(h1 << 16);
                float r3 = v.w - __uint_as_float(h1 & 0xffff0000u);
                uint32_t l0 = pack_bf16x2(r0, r1);
                uint32_t l1 = pack_bf16x2(r2, r3);
                asm volatile("st.shared.v2.b32 [%0], {%1,%2};" :: "r"(base + OFF_BH + off), "r"(h0), "r"(h1) : "memory");
                asm volatile("st.shared.v2.b32 [%0], {%1,%2};" :: "r"(base + OFF_BL + off), "r"(l0), "r"(l1) : "memory");
            }
        }
    };

    // ldmatrix lane coords (x4: m0=rows0-7/k0, m1=rows8-15/k0, m2=rows0-7/k8, m3=rows8-15/k8)
    const int lrow = (lane & 7) + ((lane >> 3) & 1) * 8;   // 0..15
    const int koff = (lane >> 4) * 8;                       // 0 or 8

    auto compute = [&](int stage) {
        const uint32_t tb = sb + stage * STAGE_B;
#pragma unroll
        for (int ks = 0; ks < 2; ks++) {
            const int k0 = ks * 16;
            uint32_t ah[2][4], al[2][4];
#pragma unroll
            for (int mt = 0; mt < 2; mt++) {
                const uint32_t row = warp_m * 32 + mt * 16 + lrow;
                const uint32_t addr = tb + OFF_AH + row * (SK * 2) + (k0 + koff) * 2;
                ldsm_x4(addr, ah[mt]);
                ldsm_x4(addr + (OFF_AL - OFF_AH), al[mt]);
            }
            uint32_t bh[4][4], blr[4][4];
#pragma unroll
            for (int nt = 0; nt < 4; nt++) {
                const uint32_t nrow = warp_n * 64 + nt * 16 + lrow;
                const uint32_t addr = tb + OFF_BH + nrow * (SK * 2) + (k0 + koff) * 2;
                ldsm_x4(addr, bh[nt]);
                ldsm_x4(addr + (OFF_BL - OFF_BH), blr[nt]);
            }
#pragma unroll
            for (int mt = 0; mt < 2; mt++)
#pragma unroll
                for (int nb = 0; nb < 8; nb++) {
                    const int nt = nb >> 1, h = nb & 1;
                    mma16816(acc[mt][nb], ah[mt], bh[nt][h], bh[nt][2 + h]);
                    mma16816(acc[mt][nb], al[mt], bh[nt][h], bh[nt][2 + h]);
                    mma16816(acc[mt][nb], ah[mt], blr[nt][h], blr[nt][2 + h]);
                }
        }
    };

    // ---- software pipeline
    issue_loads(0);
    store_smem(0);
    __syncthreads();
    for (int kc = 0; kc < nk; kc++) {
        if (kc + 1 < nk) issue_loads(kc + 1);
        compute(kc & 1);
        if (kc + 1 < nk) store_smem((kc + 1) & 1);
        __syncthreads();
    }

    // ---- epilogue: bias + relu, float2 stores
    const int qr = lane >> 2;            // 0..7
    const int qc = (lane & 3) * 2;       // 0,2,4,6
    const float* bp = bias + (size_t)e * sBiasE + ntile * 128;
    float* Cb = C + (size_t)e * sCe + ((size_t)blockIdx.x * 128) * Ntot + (size_t)ntile * 128;

#pragma unroll
    for (int mt = 0; mt < 2; mt++) {
#pragma unroll
        for (int nb = 0; nb < 8; nb++) {
            const int col = warp_n * 64 + nb * 8 + qc;
            const float b0 = __ldg(bp + col), b1 = __ldg(bp + col + 1);
            const int row0 = warp_m * 32 + mt * 16 + qr;
            float2 v0, v1;
            v0.x = fmaxf(acc[mt][nb][0] + b0, 0.f);
            v0.y = fmaxf(acc[mt][nb][1] + b1, 0.f);
            v1.x = fmaxf(acc[mt][nb][2] + b0, 0.f);
            v1.y = fmaxf(acc[mt][nb][3] + b1, 0.f);
            *reinterpret_cast<float2*>(Cb + (size_t)row0 * Ntot + col)       = v0;
            *reinterpret_cast<float2*>(Cb + (size_t)(row0 + 8) * Ntot + col) = v1;
        }
    }
}

// ---------------------------------------------------------------------------
// Router final layer + gumbel softmax (validated)
// ---------------------------------------------------------------------------
__global__ __launch_bounds__(256) void router_final_kernel(
    const float* __restrict__ C2, const float* __restrict__ rw3,
    const float* __restrict__ rb3, const float* __restrict__ u,
    float* __restrict__ weights)
{
    __shared__ float w3s[RH2_ * E_];
    __shared__ float b3s[E_];
    const int tid = threadIdx.x;
    for (int i = tid; i < RH2_ * E_; i += 256) w3s[i] = rw3[i];
    if (tid < E_) b3s[tid] = rb3[tid];
    __syncthreads();

    const int b = blockIdx.x * 256 + tid;
    float logit[E_];
#pragma unroll
    for (int e = 0; e < E_; e++) logit[e] = b3s[e];
    const float* row = C2 + (size_t)b * RH2_;
#pragma unroll 4
    for (int i = 0; i < RH2_; i++) {
        float xv = __ldg(row + i);
#pragma unroll
        for (int e = 0; e < E_; e++) logit[e] += xv * w3s[i * E_ + e];
    }
    float s[E_], m = -1e30f;
#pragma unroll
    for (int e = 0; e < E_; e++) {
        float uu = __ldg(u + (size_t)b * E_ + e);
        uu = fminf(fmaxf(uu, 1e-10f), 1.0f);
        float g = -logf(-logf(uu) + 1e-10f);
        s[e] = (logit[e] + g) * (1.0f / 3.0f);
        m = fmaxf(m, s[e]);
    }
    float sum = 0.f;
#pragma unroll
    for (int e = 0; e < E_; e++) { float ev = expf(s[e] - m); s[e] = ev; sum += ev; }
    float inv = 1.0f / sum;
#pragma unroll
    for (int e = 0; e < E_; e++) weights[(size_t)b * E_ + e] = s[e] * inv;
}

// ---------------------------------------------------------------------------
// zc[e,b,:] = h2[e,b,:] @ ew3[e] + eb3[e]   (L=2; one warp per row)
// ---------------------------------------------------------------------------
__global__ __launch_bounds__(256) void zc_kernel(
    const float* __restrict__ H2, const float* __restrict__ ew3,
    const float* __restrict__ eb3, float* __restrict__ co)
{
    __shared__ float w3[H_ * L_];
    const int e = blockIdx.y;
    const int tid = threadIdx.x, wid = tid >> 5, lid = tid & 31;
    w3[tid] = ew3[e * H_ * L_ + tid];
    __syncthreads();

    const size_t b = (size_t)blockIdx.x * 8 + wid;
    const float* row = H2 + ((size_t)e * B_ + b) * H_;
    float4 v = *reinterpret_cast<const float4*>(row + lid * 4);
    const int c = lid * 4;
    float p0 = v.x * w3[(c + 0) * 2] + v.y * w3[(c + 1) * 2] + v.z * w3[(c + 2) * 2] + v.w * w3[(c + 3) * 2];
    float p1 = v.x * w3[(c + 0) * 2 + 1] + v.y * w3[(c + 1) * 2 + 1] + v.z * w3[(c + 2) * 2 + 1] + v.w * w3[(c + 3) * 2 + 1];
#pragma unroll
    for (int o = 16; o; o >>= 1) {
        p0 += __shfl_down_sync(0xffffffff, p0, o);
        p1 += __shfl_down_sync(0xffffffff, p1, o);
    }
    if (lid == 0) {
        float* dst = co + ((size_t)e * B_ + b) * L_;
        dst[0] = p0 + eb3[e * L_ + 0];
        dst[1] = p1 + eb3[e * L_ + 1];
    }
}

// ---------------------------------------------------------------------------
// z[b,l] = sum_e weights[b,e] * co[e,b,l]
// ---------------------------------------------------------------------------
__global__ __launch_bounds__(256) void combine_kernel(
    const float* __restrict__ weights, const float* __restrict__ co,
    float* __restrict__ z)
{
    int idx = blockIdx.x * 256 + threadIdx.x;
    if (idx >= B_ * L_) return;
    int b = idx >> 1;
    float s = 0.f;
#pragma unroll
    for (int e = 0; e < E_; e++)
        s += weights[(size_t)b * E_ + e] * co[(size_t)e * (B_ * L_) + idx];
    z[idx] = s;
}

// ---------------------------------------------------------------------------
extern "C" void kernel_launch(void* const* d_in, const int* in_sizes, int n_in,
                              void* d_out, int out_size)
{
    const float* x   = (const float*)d_in[0];
    const float* u   = (const float*)d_in[1];
    const float* rw1 = (const float*)d_in[2];
    const float* rb1 = (const float*)d_in[3];
    const float* rw2 = (const float*)d_in[4];
    const float* rb2 = (const float*)d_in[5];
    const float* rw3 = (const float*)d_in[6];
    const float* rb3 = (const float*)d_in[7];
    const float* ew1 = (const float*)d_in[8];
    const float* eb1 = (const float*)d_in[9];
    const float* ew2 = (const float*)d_in[10];
    const float* eb2 = (const float*)d_in[11];
    const float* ew3 = (const float*)d_in[12];
    const float* eb3 = (const float*)d_in[13];

    float* out     = (float*)d_out;
    float* z       = out;                                // [B, L]
    float* weights = out + (size_t)B_ * L_;              // [B, E]
    float* co      = weights + (size_t)B_ * E_;          // [E, B, L]

    float *rh1, *rh2, *h1, *h2, *wt;
    cudaGetSymbolAddress((void**)&rh1, g_rh1);
    cudaGetSymbolAddress((void**)&rh2, g_rh2);
    cudaGetSymbolAddress((void**)&h1,  g_h1);
    cudaGetSymbolAddress((void**)&h2,  g_h2);
    cudaGetSymbolAddress((void**)&wt,  g_wt);

    static bool attr_done = false;
    if (!attr_done) {
        cudaFuncSetAttribute(mma_gemm_relu, cudaFuncAttributeMaxDynamicSharedMemorySize, SMEM_MMA);
        attr_done = true;
    }

    dim3 tb(32, 8);
    // Weight transposes: [K,N] -> [N,K]
    transpose_kernel<<<dim3(RH1_ / 32, D_ / 32, 1),   tb>>>(rw1, wt + WT_RW1, D_,   RH1_);
    transpose_kernel<<<dim3(RH2_ / 32, RH1_ / 32, 1), tb>>>(rw2, wt + WT_RW2, RH1_, RH2_);
    transpose_kernel<<<dim3(H_ / 32, D_ / 32, E_),    tb>>>(ew1, wt + WT_EW1, D_,   H_);
    transpose_kernel<<<dim3(H_ / 32, H_ / 32, E_),    tb>>>(ew2, wt + WT_EW2, H_,   H_);

    // Router L1: [B,512] @ [512,256] -> rh1
    mma_gemm_relu<<<dim3(B_ / 128, 1, RH1_ / 128), 256, SMEM_MMA>>>(
        x, wt + WT_RW1, rb1, rh1, D_, RH1_, 0, 0, 0, 0);
    // Router L2: [B,256] @ [256,128] -> rh2
    mma_gemm_relu<<<dim3(B_ / 128, 1, 1), 256, SMEM_MMA>>>(
        rh1, wt + WT_RW2, rb2, rh2, RH1_, RH2_, 0, 0, 0, 0);
    // Router L3 + gumbel softmax -> weights (d_out)
    router_final_kernel<<<B_ / 256, 256>>>(rh2, rw3, rb3, u, weights);

    // Expert L1 (batched over E): x @ ew1[e]^T-layout -> h1
    mma_gemm_relu<<<dim3(B_ / 128, E_, 1), 256, SMEM_MMA>>>(
        x, wt + WT_EW1, eb1, h1, D_, H_,
        0, (long long)H_ * D_, H_, (long long)B_ * H_);
    // Expert L2: h1 @ ew2[e] -> h2
    mma_gemm_relu<<<dim3(B_ / 128, E_, 1), 256, SMEM_MMA>>>(
        h1, wt + WT_EW2, eb2, h2, H_, H_,
        (long long)B_ * H_, (long long)H_ * H_, H_, (long long)B_ * H_);

    // Expert L3 -> chart_outputs (d_out)
    zc_kernel<<<dim3(B_ / 8, E_), 256>>>(h2, ew3, eb3, co);
    // Weighted combine -> z (d_out)
    combine_kernel<<<(B_ * L_ + 255) / 256, 256>>>(weights, co, z);
}

// round 15
// speedup vs baseline: 2.3923x; 1.0089x over previous
#include <cuda_runtime.h>
#include <cstdint>

// Problem constants
#define B_   32768
#define D_   512
#define E_   10
#define H_   128
#define L_   2
#define RH1_ 256
#define RH2_ 128

// ---------------------------------------------------------------------------
// Scratch (__device__ globals; allocation-free rule)
// ---------------------------------------------------------------------------
__device__ float g_rh1[(size_t)B_ * RH1_];           // 33.5 MB
__device__ float g_rh2[(size_t)B_ * RH2_];           // 16.8 MB
// transposed weights: rw1_t[256,512] | rw2_t[128,256] | ew1_t[10,128,512] | ew2_t[10,128,128]
#define WT_RW1 0
#define WT_RW2 131072
#define WT_EW1 163840
#define WT_EW2 819200
__device__ float g_wt[983040];                       // ~3.9 MB

// ---------------------------------------------------------------------------
// Helpers
// ---------------------------------------------------------------------------
__device__ __forceinline__ uint32_t smem_to_u32(const void* p) {
    uint32_t a;
    asm("{ .reg .u64 t; cvta.to.shared.u64 t, %1; cvt.u32.u64 %0, t; }" : "=r"(a) : "l"(p));
    return a;
}
__device__ __forceinline__ void ldsm_x4(uint32_t addr, uint32_t* r) {
    asm volatile("ldmatrix.sync.aligned.m8n8.x4.shared.b16 {%0,%1,%2,%3}, [%4];"
        : "=r"(r[0]), "=r"(r[1]), "=r"(r[2]), "=r"(r[3]) : "r"(addr));
}
__device__ __forceinline__ void mma16816(float* d, const uint32_t* a, uint32_t b0, uint32_t b1) {
    asm volatile("mma.sync.aligned.m16n8k16.row.col.f32.bf16.bf16.f32 "
        "{%0,%1,%2,%3}, {%4,%5,%6,%7}, {%8,%9}, {%0,%1,%2,%3};"
        : "+f"(d[0]), "+f"(d[1]), "+f"(d[2]), "+f"(d[3])
        : "r"(a[0]), "r"(a[1]), "r"(a[2]), "r"(a[3]), "r"(b0), "r"(b1));
}
// pack two fp32 -> bf16x2 (first arg lands in low half)
__device__ __forceinline__ uint32_t pack_bf16x2(float lo, float hi) {
    uint32_t r;
    asm("cvt.rn.bf16x2.f32 %0, %1, %2;" : "=r"(r) : "f"(hi), "f"(lo));
    return r;
}

// ---------------------------------------------------------------------------
// Batched transpose: in[e][K][N] -> out[e][N][K]  (K, N multiples of 32)
// ---------------------------------------------------------------------------
__global__ void transpose_kernel(const float* __restrict__ in, float* __restrict__ out,
                                 int K, int N)
{
    __shared__ float t[32][33];
    const size_t eoff = (size_t)blockIdx.z * K * N;
    const int n0 = blockIdx.x * 32, k0 = blockIdx.y * 32;
    const int tx = threadIdx.x, ty = threadIdx.y;  // 32 x 8
#pragma unroll
    for (int i = 0; i < 32; i += 8)
        t[ty + i][tx] = in[eoff + (size_t)(k0 + ty + i) * N + n0 + tx];
    __syncthreads();
#pragma unroll
    for (int i = 0; i < 32; i += 8)
        out[eoff + (size_t)(n0 + ty + i) * K + k0 + tx] = t[tx][ty + i];
}

// ---------------------------------------------------------------------------
// Shared GEMM tile constants (phase-1 staging, 32-K chunks)
// ---------------------------------------------------------------------------
#define BK      32
#define SK      40                   // padded row stride (bf16 elems) in stage
#define TILE_BYTES_ (128 * SK * 2)   // 10240
#define OFF_AH  0
#define OFF_AL  (1 * TILE_BYTES_)
#define OFF_BH  (2 * TILE_BYTES_)
#define OFF_BL  (3 * TILE_BYTES_)
#define STAGE_B (4 * TILE_BYTES_)    // 40960
#define SMEM_MMA (2 * STAGE_B)       // 81920 (router GEMM kernel)

// Fused expert kernel smem layout (dynamic):
//   [0, 81920)            phase-1 double-buffer stages; phase-2: ew2 hi at 0, ew2 lo at 34816
//   [81920, 151552)       h1 tile: hi at +0, lo at +34816   (row stride 272B)
//   [151552, 159744)      red[128][8][2] floats
//   [159744, 160768)      w3[256] floats (ew3 for this expert)
#define SK2        136               // padded row stride for 128-K tiles (bf16 elems)
#define T2_BYTES   (128 * SK2 * 2)   // 34816
#define OFF_EW2H   0
#define OFF_EW2L   T2_BYTES
#define OFF_H1H    81920
#define OFF_H1L    (81920 + T2_BYTES)
#define OFF_RED    151552
#define OFF_W3     159744
#define SMEM_FUSED 160768

// ---------------------------------------------------------------------------
// Router GEMM: bf16 3-term compensated + bias + relu via mma.sync.
// ---------------------------------------------------------------------------
__global__ __launch_bounds__(256) void mma_gemm_relu(
    const float* __restrict__ A, const float* __restrict__ Bt,
    const float* __restrict__ bias, float* __restrict__ C,
    int K, int Ntot)
{
    extern __shared__ char smem[];
    const uint32_t sb = smem_to_u32(smem);
    const int tid = threadIdx.x;
    const int lane = tid & 31, wid = tid >> 5;
    const int warp_m = wid & 3;
    const int warp_n = wid >> 2;
    const int ntile = blockIdx.z;

    const float* Ab = A + (size_t)blockIdx.x * 128 * K;
    const float* Bb = Bt + (size_t)ntile * 128 * K;

    const int gr = tid >> 3;
    const int gc = (tid & 7) << 2;

    float4 va[4], vb[4];
    const int nk = K >> 5;

    float acc[2][8][4];
#pragma unroll
    for (int mt = 0; mt < 2; mt++)
#pragma unroll
        for (int nb = 0; nb < 8; nb++)
#pragma unroll
            for (int q = 0; q < 4; q++) acc[mt][nb][q] = 0.f;

    auto issue_loads = [&](int kc) {
#pragma unroll
        for (int i = 0; i < 4; i++) {
            const int r = gr + i * 32;
            va[i] = *reinterpret_cast<const float4*>(Ab + (size_t)r * K + kc * BK + gc);
            vb[i] = *reinterpret_cast<const float4*>(Bb + (size_t)r * K + kc * BK + gc);
        }
    };
    auto store_smem = [&](int stage) {
        const uint32_t base = sb + stage * STAGE_B;
#pragma unroll
        for (int i = 0; i < 4; i++) {
            const int r = gr + i * 32;
            const uint32_t off = (uint32_t)(r * (SK * 2) + gc * 2);
            {
                float4 v = va[i];
                uint32_t h0 = pack_bf16x2(v.x, v.y);
                uint32_t h1 = pack_bf16x2(v.z, v.w);
                float r0 = v.x - __uint_as_float(h0 << 16);
                float r1 = v.y - __uint_as_float(h0 & 0xffff0000u);
                float r2 = v.z - __uint_as_float(h1 << 16);
                float r3 = v.w - __uint_as_float(h1 & 0xffff0000u);
                uint32_t l0 = pack_bf16x2(r0, r1);
                uint32_t l1 = pack_bf16x2(r2, r3);
                asm volatile("st.shared.v2.b32 [%0], {%1,%2};" :: "r"(base + OFF_AH + off), "r"(h0), "r"(h1) : "memory");
                asm volatile("st.shared.v2.b32 [%0], {%1,%2};" :: "r"(base + OFF_AL + off), "r"(l0), "r"(l1) : "memory");
            }
            {
                float4 v = vb[i];
                uint32_t h0 = pack_bf16x2(v.x, v.y);
                uint32_t h1 = pack_bf16x2(v.z, v.w);
                float r0 = v.x - __uint_as_float(h0 << 16);
                float r1 = v.y - __uint_as_float(h0 & 0xffff0000u);
                float r2 = v.z - __uint_as_float(h1 << 16);
                float r3 = v.w - __uint_as_float(h1 & 0xffff0000u);
                uint32_t l0 = pack_bf16x2(r0, r1);
                uint32_t l1 = pack_bf16x2(r2, r3);
                asm volatile("st.shared.v2.b32 [%0], {%1,%2};" :: "r"(base + OFF_BH + off), "r"(h0), "r"(h1) : "memory");
                asm volatile("st.shared.v2.b32 [%0], {%1,%2};" :: "r"(base + OFF_BL + off), "r"(l0), "r"(l1) : "memory");
            }
        }
    };

    const int lrow = (lane & 7) + ((lane >> 3) & 1) * 8;
    const int koff = (lane >> 4) * 8;

    auto compute = [&](int stage) {
        const uint32_t tb = sb + stage * STAGE_B;
#pragma unroll
        for (int ks = 0; ks < 2; ks++) {
            const int k0 = ks * 16;
            uint32_t ah[2][4], al[2][4];
#pragma unroll
            for (int mt = 0; mt < 2; mt++) {
                const uint32_t row = warp_m * 32 + mt * 16 + lrow;
                const uint32_t addr = tb + OFF_AH + row * (SK * 2) + (k0 + koff) * 2;
                ldsm_x4(addr, ah[mt]);
                ldsm_x4(addr + (OFF_AL - OFF_AH), al[mt]);
            }
            uint32_t bh[4][4], blr[4][4];
#pragma unroll
            for (int nt = 0; nt < 4; nt++) {
                const uint32_t nrow = warp_n * 64 + nt * 16 + lrow;
                const uint32_t addr = tb + OFF_BH + nrow * (SK * 2) + (k0 + koff) * 2;
                ldsm_x4(addr, bh[nt]);
                ldsm_x4(addr + (OFF_BL - OFF_BH), blr[nt]);
            }
#pragma unroll
            for (int mt = 0; mt < 2; mt++)
#pragma unroll
                for (int nb = 0; nb < 8; nb++) {
                    const int nt = nb >> 1, h = nb & 1;
                    mma16816(acc[mt][nb], ah[mt], bh[nt][h], bh[nt][2 + h]);
                    mma16816(acc[mt][nb], al[mt], bh[nt][h], bh[nt][2 + h]);
                    mma16816(acc[mt][nb], ah[mt], blr[nt][h], blr[nt][2 + h]);
                }
        }
    };

    issue_loads(0);
    store_smem(0);
    __syncthreads();
    for (int kc = 0; kc < nk; kc++) {
        if (kc + 1 < nk) issue_loads(kc + 1);
        compute(kc & 1);
        if (kc + 1 < nk) store_smem((kc + 1) & 1);
        __syncthreads();
    }

    const int qr = lane >> 2;
    const int qc = (lane & 3) * 2;
    const float* bp = bias + ntile * 128;
    float* Cb = C + ((size_t)blockIdx.x * 128) * Ntot + (size_t)ntile * 128;

#pragma unroll
    for (int mt = 0; mt < 2; mt++) {
#pragma unroll
        for (int nb = 0; nb < 8; nb++) {
            const int col = warp_n * 64 + nb * 8 + qc;
            const float b0 = __ldg(bp + col), b1 = __ldg(bp + col + 1);
            const int row0 = warp_m * 32 + mt * 16 + qr;
            float2 v0, v1;
            v0.x = fmaxf(acc[mt][nb][0] + b0, 0.f);
            v0.y = fmaxf(acc[mt][nb][1] + b1, 0.f);
            v1.x = fmaxf(acc[mt][nb][2] + b0, 0.f);
            v1.y = fmaxf(acc[mt][nb][3] + b1, 0.f);
            *reinterpret_cast<float2*>(Cb + (size_t)row0 * Ntot + col)       = v0;
            *reinterpret_cast<float2*>(Cb + (size_t)(row0 + 8) * Ntot + col) = v1;
        }
    }
}

// ---------------------------------------------------------------------------
// Fused expert kernel: L1 (K=512 GEMM, h1 stays in SMEM) -> L2 (K=128 GEMM)
// -> L3 (zc, L=2) -> chart_outputs.  grid = (B/128, E).
// ---------------------------------------------------------------------------
__global__ __launch_bounds__(256) void expert_fused(
    const float* __restrict__ x, const float* __restrict__ ew1t,
    const float* __restrict__ eb1, const float* __restrict__ ew2t,
    const float* __restrict__ eb2, const float* __restrict__ ew3,
    const float* __restrict__ eb3, float* __restrict__ co)
{
    extern __shared__ char smem[];
    const uint32_t sb = smem_to_u32(smem);
    const int tid = threadIdx.x;
    const int lane = tid & 31, wid = tid >> 5;
    const int warp_m = wid & 3;
    const int warp_n = wid >> 2;
    const int e = blockIdx.y;

    const float* Ab = x + (size_t)blockIdx.x * 128 * D_;
    const float* Bb = ew1t + (size_t)e * H_ * D_;

    const int gr = tid >> 3;
    const int gc = (tid & 7) << 2;

    // w3 (ew3[e], [128][2]) to smem
    *reinterpret_cast<float*>(smem + OFF_W3 + tid * 4) = ew3[e * H_ * L_ + tid];

    float4 va[4], vb[4];

    float acc[2][8][4];
#pragma unroll
    for (int mt = 0; mt < 2; mt++)
#pragma unroll
        for (int nb = 0; nb < 8; nb++)
#pragma unroll
            for (int q = 0; q < 4; q++) acc[mt][nb][q] = 0.f;

    auto issue_loads = [&](int kc) {
#pragma unroll
        for (int i = 0; i < 4; i++) {
            const int r = gr + i * 32;
            va[i] = *reinterpret_cast<const float4*>(Ab + (size_t)r * D_ + kc * BK + gc);
            vb[i] = *reinterpret_cast<const float4*>(Bb + (size_t)r * D_ + kc * BK + gc);
        }
    };
    auto store_smem = [&](int stage) {
        const uint32_t base = sb + stage * STAGE_B;
#pragma unroll
        for (int i = 0; i < 4; i++) {
            const int r = gr + i * 32;
            const uint32_t off = (uint32_t)(r * (SK * 2) + gc * 2);
            {
                float4 v = va[i];
                uint32_t h0 = pack_bf16x2(v.x, v.y);
                uint32_t h1 = pack_bf16x2(v.z, v.w);
                float r0 = v.x - __uint_as_float(h0 << 16);
                float r1 = v.y - __uint_as_float(h0 & 0xffff0000u);
                float r2 = v.z - __uint_as_float(h1 << 16);
                float r3 = v.w - __uint_as_float(h1 & 0xffff0000u);
                uint32_t l0 = pack_bf16x2(r0, r1);
                uint32_t l1 = pack_bf16x2(r2, r3);
                asm volatile("st.shared.v2.b32 [%0], {%1,%2};" :: "r"(base + OFF_AH + off), "r"(h0), "r"(h1) : "memory");
                asm volatile("st.shared.v2.b32 [%0], {%1,%2};" :: "r"(base + OFF_AL + off), "r"(l0), "r"(l1) : "memory");
            }
            {
                float4 v = vb[i];
                uint32_t h0 = pack_bf16x2(v.x, v.y);
                uint32_t h1 = pack_bf16x2(v.z, v.w);
                float r0 = v.x - __uint_as_float(h0 << 16);
                float r1 = v.y - __uint_as_float(h0 & 0xffff0000u);
                float r2 = v.z - __uint_as_float(h1 << 16);
                float r3 = v.w - __uint_as_float(h1 & 0xffff0000u);
                uint32_t l0 = pack_bf16x2(r0, r1);
                uint32_t l1 = pack_bf16x2(r2, r3);
                asm volatile("st.shared.v2.b32 [%0], {%1,%2};" :: "r"(base + OFF_BH + off), "r"(h0), "r"(h1) : "memory");
                asm volatile("st.shared.v2.b32 [%0], {%1,%2};" :: "r"(base + OFF_BL + off), "r"(l0), "r"(l1) : "memory");
            }
        }
    };

    const int lrow = (lane & 7) + ((lane >> 3) & 1) * 8;
    const int koff = (lane >> 4) * 8;

    auto compute = [&](int stage) {
        const uint32_t tb = sb + stage * STAGE_B;
#pragma unroll
        for (int ks = 0; ks < 2; ks++) {
            const int k0 = ks * 16;
            uint32_t ah[2][4], al[2][4];
#pragma unroll
            for (int mt = 0; mt < 2; mt++) {
                const uint32_t row = warp_m * 32 + mt * 16 + lrow;
                const uint32_t addr = tb + OFF_AH + row * (SK * 2) + (k0 + koff) * 2;
                ldsm_x4(addr, ah[mt]);
                ldsm_x4(addr + (OFF_AL - OFF_AH), al[mt]);
            }
            uint32_t bh[4][4], blr[4][4];
#pragma unroll
            for (int nt = 0; nt < 4; nt++) {
                const uint32_t nrow = warp_n * 64 + nt * 16 + lrow;
                const uint32_t addr = tb + OFF_BH + nrow * (SK * 2) + (k0 + koff) * 2;
                ldsm_x4(addr, bh[nt]);
                ldsm_x4(addr + (OFF_BL - OFF_BH), blr[nt]);
            }
#pragma unroll
            for (int mt = 0; mt < 2; mt++)
#pragma unroll
                for (int nb = 0; nb < 8; nb++) {
                    const int nt = nb >> 1, h = nb & 1;
                    mma16816(acc[mt][nb], ah[mt], bh[nt][h], bh[nt][2 + h]);
                    mma16816(acc[mt][nb], al[mt], bh[nt][h], bh[nt][2 + h]);
                    mma16816(acc[mt][nb], ah[mt], blr[nt][h], blr[nt][2 + h]);
                }
        }
    };

    // ---- Phase 1: h1 = relu(x @ ew1t^T + eb1), K=512
    issue_loads(0);
    store_smem(0);
    __syncthreads();
    const int nk = D_ >> 5;
    for (int kc = 0; kc < nk; kc++) {
        if (kc + 1 < nk) issue_loads(kc + 1);
        compute(kc & 1);
        if (kc + 1 < nk) store_smem((kc + 1) & 1);
        __syncthreads();
    }
    // stage buffers now free (last compute done, syncthreads passed)

    // ---- Phase 1 epilogue: bias+relu, bf16 hi/lo split -> h1 SMEM (stride 272B)
    const int qr = lane >> 2;
    const int qc = (lane & 3) * 2;
    const float* b1p = eb1 + e * H_;
#pragma unroll
    for (int mt = 0; mt < 2; mt++) {
#pragma unroll
        for (int nb = 0; nb < 8; nb++) {
            const int col = warp_n * 64 + nb * 8 + qc;
            const float b0 = __ldg(b1p + col), b1v = __ldg(b1p + col + 1);
#pragma unroll
            for (int half = 0; half < 2; half++) {
                const int row = warp_m * 32 + mt * 16 + qr + half * 8;
                float v0 = fmaxf(acc[mt][nb][half * 2 + 0] + b0, 0.f);
                float v1 = fmaxf(acc[mt][nb][half * 2 + 1] + b1v, 0.f);
                uint32_t hh = pack_bf16x2(v0, v1);
                float r0 = v0 - __uint_as_float(hh << 16);
                float r1 = v1 - __uint_as_float(hh & 0xffff0000u);
                uint32_t ll = pack_bf16x2(r0, r1);
                const uint32_t off = (uint32_t)(row * (SK2 * 2) + col * 2);
                asm volatile("st.shared.b32 [%0], %1;" :: "r"(sb + OFF_H1H + off), "r"(hh) : "memory");
                asm volatile("st.shared.b32 [%0], %1;" :: "r"(sb + OFF_H1L + off), "r"(ll) : "memory");
            }
        }
    }

    // ---- Load ew2t[e] (128 N-rows x 128 K) -> bf16 hi/lo SMEM (reuse stages)
    {
        const float* W2 = ew2t + (size_t)e * H_ * H_;
#pragma unroll
        for (int i = 0; i < 16; i++) {
            const int id = tid + i * 256;           // 0..4095 float4s
            const int r = id >> 5;                  // 0..127
            const int c4 = (id & 31) << 2;          // 0..124
            float4 v = *reinterpret_cast<const float4*>(W2 + (size_t)r * H_ + c4);
            uint32_t h0 = pack_bf16x2(v.x, v.y);
            uint32_t h1 = pack_bf16x2(v.z, v.w);
            float r0 = v.x - __uint_as_float(h0 << 16);
            float r1 = v.y - __uint_as_float(h0 & 0xffff0000u);
            float r2 = v.z - __uint_as_float(h1 << 16);
            float r3 = v.w - __uint_as_float(h1 & 0xffff0000u);
            uint32_t l0 = pack_bf16x2(r0, r1);
            uint32_t l1 = pack_bf16x2(r2, r3);
            const uint32_t off = (uint32_t)(r * (SK2 * 2) + c4 * 2);
            asm volatile("st.shared.v2.b32 [%0], {%1,%2};" :: "r"(sb + OFF_EW2H + off), "r"(h0), "r"(h1) : "memory");
            asm volatile("st.shared.v2.b32 [%0], {%1,%2};" :: "r"(sb + OFF_EW2L + off), "r"(l0), "r"(l1) : "memory");
        }
    }
    __syncthreads();

    // ---- Phase 2: h2 = relu(h1 @ ew2t^T + eb2), K=128, all from SMEM
    float acc2[2][8][4];
#pragma unroll
    for (int mt = 0; mt < 2; mt++)
#pragma unroll
        for (int nb = 0; nb < 8; nb++)
#pragma unroll
            for (int q = 0; q < 4; q++) acc2[mt][nb][q] = 0.f;

#pragma unroll
    for (int ks = 0; ks < 8; ks++) {
        const int k0 = ks * 16;
        uint32_t ah[2][4], al[2][4];
#pragma unroll
        for (int mt = 0; mt < 2; mt++) {
            const uint32_t row = warp_m * 32 + mt * 16 + lrow;
            const uint32_t addr = sb + OFF_H1H + row * (SK2 * 2) + (k0 + koff) * 2;
            ldsm_x4(addr, ah[mt]);
            ldsm_x4(addr + (OFF_H1L - OFF_H1H), al[mt]);
        }
        uint32_t bh[4][4], blr[4][4];
#pragma unroll
        for (int nt = 0; nt < 4; nt++) {
            const uint32_t nrow = warp_n * 64 + nt * 16 + lrow;
            const uint32_t addr = sb + OFF_EW2H + nrow * (SK2 * 2) + (k0 + koff) * 2;
            ldsm_x4(addr, bh[nt]);
            ldsm_x4(addr + (OFF_EW2L - OFF_EW2H), blr[nt]);
        }
#pragma unroll
        for (int mt = 0; mt < 2; mt++)
#pragma unroll
            for (int nb = 0; nb < 8; nb++) {
                const int nt = nb >> 1, h = nb & 1;
                mma16816(acc2[mt][nb], ah[mt], bh[nt][h], bh[nt][2 + h]);
                mma16816(acc2[mt][nb], al[mt], bh[nt][h], bh[nt][2 + h]);
                mma16816(acc2[mt][nb], ah[mt], blr[nt][h], blr[nt][2 + h]);
            }
    }

    // ---- Phase 3: bias+relu; zc partials over this thread's 16 cols
    const float* b2p = eb2 + e * H_;
    const float* w3 = reinterpret_cast<const float*>(smem + OFF_W3);
    float* red = reinterpret_cast<float*>(smem + OFF_RED);   // [128][8][2]
    const int slot = warp_n * 4 + (lane & 3);

#pragma unroll
    for (int mt = 0; mt < 2; mt++) {
#pragma unroll
        for (int half = 0; half < 2; half++) {
            const int row = warp_m * 32 + mt * 16 + qr + half * 8;
            float p0 = 0.f, p1 = 0.f;
#pragma unroll
            for (int nb = 0; nb < 8; nb++) {
                const int col = warp_n * 64 + nb * 8 + qc;
                float h2a = fmaxf(acc2[mt][nb][half * 2 + 0] + __ldg(b2p + col), 0.f);
                float h2b = fmaxf(acc2[mt][nb][half * 2 + 1] + __ldg(b2p + col + 1), 0.f);
                p0 += h2a * w3[col * 2 + 0] + h2b * w3[(col + 1) * 2 + 0];
                p1 += h2a * w3[col * 2 + 1] + h2b * w3[(col + 1) * 2 + 1];
            }
            red[row * 16 + slot * 2 + 0] = p0;
            red[row * 16 + slot * 2 + 1] = p1;
        }
    }
    __syncthreads();

    // 256 threads -> 128 rows x 2 L outputs
    {
        const int row = tid >> 1;
        const int l = tid & 1;
        float s = eb3[e * L_ + l];
#pragma unroll
        for (int t = 0; t < 8; t++) s += red[row * 16 + t * 2 + l];
        const size_t gb = (size_t)blockIdx.x * 128 + row;
        co[(size_t)e * B_ * L_ + gb * L_ + l] = s;
    }
}

// ---------------------------------------------------------------------------
// Router final layer + gumbel softmax (validated)
// ---------------------------------------------------------------------------
__global__ __launch_bounds__(256) void router_final_kernel(
    const float* __restrict__ C2, const float* __restrict__ rw3,
    const float* __restrict__ rb3, const float* __restrict__ u,
    float* __restrict__ weights)
{
    __shared__ float w3s[RH2_ * E_];
    __shared__ float b3s[E_];
    const int tid = threadIdx.x;
    for (int i = tid; i < RH2_ * E_; i += 256) w3s[i] = rw3[i];
    if (tid < E_) b3s[tid] = rb3[tid];
    __syncthreads();

    const int b = blockIdx.x * 256 + tid;
    float logit[E_];
#pragma unroll
    for (int e = 0; e < E_; e++) logit[e] = b3s[e];
    const float* row = C2 + (size_t)b * RH2_;
#pragma unroll 4
    for (int i = 0; i < RH2_; i++) {
        float xv = __ldg(row + i);
#pragma unroll
        for (int e = 0; e < E_; e++) logit[e] += xv * w3s[i * E_ + e];
    }
    float s[E_], m = -1e30f;
#pragma unroll
    for (int e = 0; e < E_; e++) {
        float uu = __ldg(u + (size_t)b * E_ + e);
        uu = fminf(fmaxf(uu, 1e-10f), 1.0f);
        float g = -logf(-logf(uu) + 1e-10f);
        s[e] = (logit[e] + g) * (1.0f / 3.0f);
        m = fmaxf(m, s[e]);
    }
    float sum = 0.f;
#pragma unroll
    for (int e = 0; e < E_; e++) { float ev = expf(s[e] - m); s[e] = ev; sum += ev; }
    float inv = 1.0f / sum;
#pragma unroll
    for (int e = 0; e < E_; e++) weights[(size_t)b * E_ + e] = s[e] * inv;
}

// ---------------------------------------------------------------------------
// z[b,l] = sum_e weights[b,e] * co[e,b,l]
// ---------------------------------------------------------------------------
__global__ __launch_bounds__(256) void combine_kernel(
    const float* __restrict__ weights, const float* __restrict__ co,
    float* __restrict__ z)
{
    int idx = blockIdx.x * 256 + threadIdx.x;
    if (idx >= B_ * L_) return;
    int b = idx >> 1;
    float s = 0.f;
#pragma unroll
    for (int e = 0; e < E_; e++)
        s += weights[(size_t)b * E_ + e] * co[(size_t)e * (B_ * L_) + idx];
    z[idx] = s;
}

// ---------------------------------------------------------------------------
extern "C" void kernel_launch(void* const* d_in, const int* in_sizes, int n_in,
                              void* d_out, int out_size)
{
    const float* x   = (const float*)d_in[0];
    const float* u   = (const float*)d_in[1];
    const float* rw1 = (const float*)d_in[2];
    const float* rb1 = (const float*)d_in[3];
    const float* rw2 = (const float*)d_in[4];
    const float* rb2 = (const float*)d_in[5];
    const float* rw3 = (const float*)d_in[6];
    const float* rb3 = (const float*)d_in[7];
    const float* ew1 = (const float*)d_in[8];
    const float* eb1 = (const float*)d_in[9];
    const float* ew2 = (const float*)d_in[10];
    const float* eb2 = (const float*)d_in[11];
    const float* ew3 = (const float*)d_in[12];
    const float* eb3 = (const float*)d_in[13];

    float* out     = (float*)d_out;
    float* z       = out;                                // [B, L]
    float* weights = out + (size_t)B_ * L_;              // [B, E]
    float* co      = weights + (size_t)B_ * E_;          // [E, B, L]

    float *rh1, *rh2, *wt;
    cudaGetSymbolAddress((void**)&rh1, g_rh1);
    cudaGetSymbolAddress((void**)&rh2, g_rh2);
    cudaGetSymbolAddress((void**)&wt,  g_wt);

    static bool attr_done = false;
    if (!attr_done) {
        cudaFuncSetAttribute(mma_gemm_relu, cudaFuncAttributeMaxDynamicSharedMemorySize, SMEM_MMA);
        cudaFuncSetAttribute(expert_fused, cudaFuncAttributeMaxDynamicSharedMemorySize, SMEM_FUSED);
        attr_done = true;
    }

    dim3 tb(32, 8);
    // Weight transposes: [K,N] -> [N,K]
    transpose_kernel<<<dim3(RH1_ / 32, D_ / 32, 1),   tb>>>(rw1, wt + WT_RW1, D_,   RH1_);
    transpose_kernel<<<dim3(RH2_ / 32, RH1_ / 32, 1), tb>>>(rw2, wt + WT_RW2, RH1_, RH2_);
    transpose_kernel<<<dim3(H_ / 32, D_ / 32, E_),    tb>>>(ew1, wt + WT_EW1, D_,   H_);
    transpose_kernel<<<dim3(H_ / 32, H_ / 32, E_),    tb>>>(ew2, wt + WT_EW2, H_,   H_);

    // Router L1: [B,512] @ [512,256] -> rh1
    mma_gemm_relu<<<dim3(B_ / 128, 1, RH1_ / 128), 256, SMEM_MMA>>>(
        x, wt + WT_RW1, rb1, rh1, D_, RH1_);
    // Router L2: [B,256] @ [256,128] -> rh2
    mma_gemm_relu<<<dim3(B_ / 128, 1, 1), 256, SMEM_MMA>>>(
        rh1, wt + WT_RW2, rb2, rh2, RH1_, RH2_);
    // Router L3 + gumbel softmax -> weights (d_out)
    router_final_kernel<<<B_ / 256, 256>>>(rh2, rw3, rb3, u, weights);

    // Fused experts: L1+L2+L3 -> chart_outputs (d_out)
    expert_fused<<<dim3(B_ / 128, E_), 256, SMEM_FUSED>>>(
        x, wt + WT_EW1, eb1, wt + WT_EW2, eb2, ew3, eb3, co);

    // Weighted combine -> z (d_out)
    combine_kernel<<<(B_ * L_ + 255) / 256, 256>>>(weights, co, z);
}